// round 14
// baseline (speedup 1.0000x reference)
#include <cuda_runtime.h>
#include <cuda_fp16.h>
#include <cstdint>

// out[i,j] = exp(-(||H1_i||^2 + ||H2_j||^2 - 2*H1_i.H2_j)),  H1,H2: [8192,64] f32.
//
// Round 13: persistent kernel. 444 CTAs (3/SM), each owns ~9 contiguous
// (128x128) tile units ordered j-major: B tile + fragments + column norms
// loaded ~once per CTA; A tiles double-buffered via TMA prefetch (issue for
// u+2 after unit u's sync). Norms pre-scaled by LOG2E in prep; n1 via __ldg.

#define NR    8192
#define KDIM  64
#define LOG2E 1.4426950408889634f
#define NUNITS 4096            // (8192/128)^2

// ---- device scratch: fp16 row images, 128-row blocks of 16KB, pre-swizzled ----
__device__ __align__(1024) uint8_t g_H1s[(size_t)NR * 128];
__device__ __align__(1024) uint8_t g_H2s[(size_t)NR * 128];
__device__ float g_norm1[NR];   // pre-multiplied by LOG2E
__device__ float g_norm2[NR];   // pre-multiplied by LOG2E

// ============================ PTX helpers ============================
__device__ __forceinline__ uint32_t smem_u32(const void* p) {
    uint32_t a;
    asm("{ .reg .u64 t; cvta.to.shared.u64 t, %1; cvt.u32.u64 %0, t; }" : "=r"(a) : "l"(p));
    return a;
}
__device__ __forceinline__ float ex2f(float x) {
    float y; asm("ex2.approx.ftz.f32 %0, %1;" : "=f"(y) : "f"(x)); return y;
}
__device__ __forceinline__ void ldsm_x4(uint32_t& r0, uint32_t& r1, uint32_t& r2, uint32_t& r3,
                                        uint32_t addr) {
    asm volatile("ldmatrix.sync.aligned.m8n8.x4.shared.b16 {%0,%1,%2,%3}, [%4];"
                 : "=r"(r0), "=r"(r1), "=r"(r2), "=r"(r3) : "r"(addr));
}
__device__ __forceinline__ void mma16816(float& c0, float& c1, float& c2, float& c3,
                                         uint32_t a0, uint32_t a1, uint32_t a2, uint32_t a3,
                                         uint32_t b0, uint32_t b1) {
    asm volatile(
        "mma.sync.aligned.m16n8k16.row.col.f32.f16.f16.f32 "
        "{%0,%1,%2,%3}, {%4,%5,%6,%7}, {%8,%9}, {%0,%1,%2,%3};"
        : "+f"(c0), "+f"(c1), "+f"(c2), "+f"(c3)
        : "r"(a0), "r"(a1), "r"(a2), "r"(a3), "r"(b0), "r"(b1));
}
#define MBAR_INIT(mbar, cnt) \
    asm volatile("mbarrier.init.shared.b64 [%0], %1;" :: "r"((uint32_t)(mbar)), "r"((uint32_t)(cnt)) : "memory")
#define MBAR_EXPECT_TX(mbar, bytes) \
    asm volatile("mbarrier.arrive.expect_tx.shared.b64 _, [%0], %1;" \
                 :: "r"((uint32_t)(mbar)), "r"((uint32_t)(bytes)) : "memory")
#define BULK_G2S(dst, src, bytes, mbar) \
    asm volatile("cp.async.bulk.shared::cta.global.mbarrier::complete_tx::bytes [%0], [%1], %2, [%3];" \
                 :: "r"((uint32_t)(dst)), "l"(src), "r"((uint32_t)(bytes)), "r"((uint32_t)(mbar)) : "memory")
__device__ __forceinline__ void mbar_wait(uint32_t mbar, uint32_t parity) {
    asm volatile(
        "{\n\t.reg .pred P;\n\t"
        "W%=:\n\t"
        "mbarrier.try_wait.parity.acquire.cta.shared::cta.b64 P, [%0], %1, 0x989680;\n\t"
        "@P bra.uni D%=;\n\t"
        "bra.uni W%=;\n\t"
        "D%=:\n\t}"
        :: "r"(mbar), "r"(parity) : "memory");
}

// ============================ pre-kernel ============================
__global__ void prep_kernel(const float* __restrict__ H1, const float* __restrict__ H2, int n1) {
    int gid = blockIdx.x * blockDim.x + threadIdx.x;
    int row = gid >> 4;
    int q   = gid & 15;                 // float4 chunk: k = 4q..4q+3
    bool isA = row < n1;
    int r = isA ? row : row - n1;
    const float* src = isA ? H1 : H2;
    float4 v = reinterpret_cast<const float4*>(src)[(size_t)r * 16 + q];

    float x[4] = {v.x, v.y, v.z, v.w};
    uint32_t hu[4];
    float ss = 0.f;
    #pragma unroll
    for (int e = 0; e < 4; e++) {
        hu[e] = (uint32_t)__half_as_ushort(__float2half_rn(x[e]));
        ss = fmaf(x[e], x[e], ss);
    }
    uint2 hi = make_uint2(hu[0] | (hu[1] << 16), hu[2] | (hu[3] << 16));

    int ib = r >> 7, lr = r & 127;
    if (!isA) {
        // permute within each 32-row group so lane t's fragment columns are
        // the contiguous actual columns 8t..8t+7.
        int a = lr & 31;
        int l = (((a >> 1) & 3) << 3) | (((a >> 3) & 3) << 1) | (a & 1);
        lr = (lr & ~31) | l;
    }
    int chunk = q >> 1;
    int swc = chunk ^ (lr & 7);               // XOR swizzle for ldmatrix
    size_t off = (size_t)ib * 16384 + (size_t)lr * 128 + swc * 16 + (q & 1) * 8;
    uint8_t* base = isA ? g_H1s : g_H2s;
    *reinterpret_cast<uint2*>(base + off) = hi;

    #pragma unroll
    for (int o = 8; o; o >>= 1) ss += __shfl_xor_sync(0xffffffffu, ss, o, 16);
    if (q == 0) (isA ? g_norm1 : g_norm2)[r] = ss * LOG2E;   // pre-scaled
}

// ============================ main kernel ============================
// smem: A double buffer 2x16KB | B 16KB | 3 mbarriers
#define SM_A     0
#define SM_B     32768
#define SM_MBB   49152
#define SM_MBA0  49160
#define SM_MBA1  49168
#define SM_TOT   49280

__global__ __launch_bounds__(256, 3) void gk_mma(float* __restrict__ out) {
    extern __shared__ uint8_t smem[];
    const uint32_t sb = smem_u32(smem);
    const int tid  = threadIdx.x;
    const int wid  = tid >> 5;
    const int lane = tid & 31;

    // contiguous chunk of units for this CTA (j-major: jb = u>>6, ib = u&63)
    const int G = gridDim.x;
    const int s = (int)(((long long)blockIdx.x * NUNITS) / G);
    const int e = (int)(((long long)(blockIdx.x + 1) * NUNITS) / G);

    if (tid == 0) {
        MBAR_INIT(sb + SM_MBB, 1);
        MBAR_INIT(sb + SM_MBA0, 1);
        MBAR_INIT(sb + SM_MBA1, 1);
    }
    __syncthreads();

    // prologue: prefetch A for units s and s+1
    if (tid == 0) {
        MBAR_EXPECT_TX(sb + SM_MBA0, 16384u);
        BULK_G2S(sb + SM_A, g_H1s + (size_t)(s & 63) * 16384, 16384u, sb + SM_MBA0);
        if (s + 1 < e) {
            MBAR_EXPECT_TX(sb + SM_MBA1, 16384u);
            BULK_G2S(sb + SM_A + 16384, g_H1s + (size_t)((s + 1) & 63) * 16384, 16384u, sb + SM_MBA1);
        }
    }

    // warp tile: 64 rows x 32 cols.  wr in {0,1}, wc in {0..3}
    const int wr = wid & 1;
    const int wc = wid >> 1;
    const uint32_t aKbit = (uint32_t)(lane >> 4);
    const uint32_t bKbit = (uint32_t)((lane >> 3) & 1);

    // epilogue lane mapping (B-permuted layout)
    const int t  = lane & 3;
    const int g  = lane >> 2;
    const bool hi_g = (g >= 4);
    const int  gl   = g & 3;
    const int colb = wc * 32 + t * 8;

    // B fragment smem addressing (fixed per warp)
    uint32_t bRow[2], bXorV[2];
    #pragma unroll
    for (int ng = 0; ng < 2; ng++) {
        int nb = wc * 32 + ng * 16 + (lane & 7) + ((lane >> 4) & 1) * 8;
        bRow[ng] = sb + SM_B + nb * 128;
        bXorV[ng] = (uint32_t)(nb & 7);
    }

    uint32_t bF[4][2][4];     // resident B fragments
    float cnv[8];             // resident column norms (pre-scaled)
    int curJb = -1;
    int aph0 = 0, aph1 = 0, bph = 0;

    for (int u = s; u < e; u++) {
        const int jb = u >> 6;
        const int ib = u & 63;

        if (jb != curJb) {
            __syncthreads();          // all warps done with old B smem
            if (tid == 0) {
                MBAR_EXPECT_TX(sb + SM_MBB, 16384u);
                BULK_G2S(sb + SM_B, g_H2s + (size_t)jb * 16384, 16384u, sb + SM_MBB);
            }
            mbar_wait(sb + SM_MBB, bph); bph ^= 1;
            #pragma unroll
            for (int kc = 0; kc < 4; kc++)
                #pragma unroll
                for (int ng = 0; ng < 2; ng++) {
                    uint32_t ch = (2u * kc + bKbit) ^ bXorV[ng];
                    ldsm_x4(bF[kc][ng][0], bF[kc][ng][1], bF[kc][ng][2], bF[kc][ng][3],
                            bRow[ng] + (ch << 4));
                }
            #pragma unroll
            for (int j = 0; j < 8; j++)
                cnv[j] = __ldg(&g_norm2[jb * 128 + colb + j]);
            curJb = jb;
        }

        const int buf = (u - s) & 1;
        if (buf == 0) { mbar_wait(sb + SM_MBA0, aph0); aph0 ^= 1; }
        else          { mbar_wait(sb + SM_MBA1, aph1); aph1 ^= 1; }
        const uint32_t aBlk = sb + SM_A + buf * 16384;
        const int iT = ib * 128;
        const int jT = jb * 128;

        #pragma unroll
        for (int mi = 0; mi < 4; mi++) {
            const int ra = wr * 64 + mi * 16 + (lane & 15);
            const uint32_t aBase = aBlk + ra * 128;
            const uint32_t aXr   = (uint32_t)(ra & 7);

            float acc[4][4];
            #pragma unroll
            for (int ni = 0; ni < 4; ni++)
                #pragma unroll
                for (int f = 0; f < 4; f++) acc[ni][f] = 0.f;

            #pragma unroll
            for (int kc = 0; kc < 4; kc++) {
                uint32_t aF[4];
                uint32_t ch = (2u * kc + aKbit) ^ aXr;
                ldsm_x4(aF[0], aF[1], aF[2], aF[3], aBase + (ch << 4));
                #pragma unroll
                for (int ni = 0; ni < 4; ni++)
                    mma16816(acc[ni][0], acc[ni][1], acc[ni][2], acc[ni][3],
                             aF[0], aF[1], aF[2], aF[3],
                             bF[kc][ni >> 1][(ni & 1) * 2], bF[kc][ni >> 1][(ni & 1) * 2 + 1]);
            }

            // epilogue for this mi
            const int lr0 = wr * 64 + mi * 16 + g;
            const float rnA = __ldg(&g_norm1[iT + lr0]);
            const float rnB = __ldg(&g_norm1[iT + lr0 + 8]);

            #pragma unroll
            for (int half = 0; half < 2; half++) {
                const float rn = half ? rnB : rnA;
                float4 w0, w1;
                w0.x = ex2f(fmaf(acc[0][half * 2 + 0], 2.f * LOG2E, -rn) - cnv[0]);
                w0.y = ex2f(fmaf(acc[0][half * 2 + 1], 2.f * LOG2E, -rn) - cnv[1]);
                w0.z = ex2f(fmaf(acc[1][half * 2 + 0], 2.f * LOG2E, -rn) - cnv[2]);
                w0.w = ex2f(fmaf(acc[1][half * 2 + 1], 2.f * LOG2E, -rn) - cnv[3]);
                w1.x = ex2f(fmaf(acc[2][half * 2 + 0], 2.f * LOG2E, -rn) - cnv[4]);
                w1.y = ex2f(fmaf(acc[2][half * 2 + 1], 2.f * LOG2E, -rn) - cnv[5]);
                w1.z = ex2f(fmaf(acc[3][half * 2 + 0], 2.f * LOG2E, -rn) - cnv[6]);
                w1.w = ex2f(fmaf(acc[3][half * 2 + 1], 2.f * LOG2E, -rn) - cnv[7]);

                float4 w1x;   // xor(16) row-merge -> 4-wavefront STGs
                w1x.x = __shfl_xor_sync(0xffffffffu, w1.x, 16);
                w1x.y = __shfl_xor_sync(0xffffffffu, w1.y, 16);
                w1x.z = __shfl_xor_sync(0xffffffffu, w1.z, 16);
                w1x.w = __shfl_xor_sync(0xffffffffu, w1.w, 16);

                const int Rbase = iT + wr * 64 + mi * 16 + half * 8;
                {   // rows Rbase..Rbase+3
                    float4 v = hi_g ? w1x : w0;
                    int col = colb + (hi_g ? 4 : 0);
                    __stcs(reinterpret_cast<float4*>(out + (size_t)(Rbase + gl) * NR + jT + col), v);
                }
                {   // rows Rbase+4..Rbase+7
                    float4 v = hi_g ? w0 : w1x;
                    int col = colb + (hi_g ? 0 : 4);
                    __stcs(reinterpret_cast<float4*>(out + (size_t)(Rbase + gl + 4) * NR + jT + col), v);
                }
            }
        }

        __syncthreads();              // all warps done reading A buf
        if (u + 2 < e && tid == 0) {  // prefetch A for u+2 into this buf
            uint32_t mb = (buf == 0) ? (sb + SM_MBA0) : (sb + SM_MBA1);
            MBAR_EXPECT_TX(mb, 16384u);
            BULK_G2S(sb + SM_A + buf * 16384, g_H1s + (size_t)((u + 2) & 63) * 16384, 16384u, mb);
        }
    }
}

// ============================ launch ============================
extern "C" void kernel_launch(void* const* d_in, const int* in_sizes, int n_in,
                              void* d_out, int out_size)
{
    const float* H1 = (const float*)d_in[0];
    const float* H2 = (const float*)d_in[1];
    float* out = (float*)d_out;

    int n1 = in_sizes[0] / KDIM;   // 8192
    int n2 = in_sizes[1] / KDIM;   // 8192

    prep_kernel<<<(n1 + n2) * 16 / 256, 256>>>(H1, H2, n1);

    static bool attr_set = false;
    if (!attr_set) {
        cudaFuncSetAttribute(gk_mma, cudaFuncAttributeMaxDynamicSharedMemorySize, SM_TOT);
        attr_set = true;
    }
    gk_mma<<<444, 256, SM_TOT>>>(out);   // 3 CTAs/SM x 148 SMs
}

// round 15
// speedup vs baseline: 1.1667x; 1.1667x over previous
#include <cuda_runtime.h>
#include <cuda_fp16.h>
#include <cstdint>

// out[i,j] = exp(-(||H1_i||^2 + ||H2_j||^2 - 2*H1_i.H2_j)),  H1,H2: [8192,64] f32.
//
// Round 15: R12 mainloop (best: fp16 single-term mma.sync, B-reuse over 2
// i-blocks, xor(16)-merged 4-wavefront stores) in a SINGLE launch: the fp32->
// fp16 pre-swizzle conversion runs inside gk_mma on CTAs lin<128 (wave-1
// guaranteed), consumers acquire-poll per-block flags before their TMA loads.
// Split A/B mbarriers overlap bF LDSM with the A tile arrival. Norms are
// pre-scaled by LOG2E at conversion.

#define NR    8192
#define KDIM  64
#define LOG2E 1.4426950408889634f

// ---- device scratch: fp16 row images, 128-row blocks of 16KB, pre-swizzled ----
__device__ __align__(1024) uint8_t g_H1s[(size_t)NR * 128];
__device__ __align__(1024) uint8_t g_H2s[(size_t)NR * 128];
__device__ float g_norm1[NR];   // pre-scaled by LOG2E
__device__ float g_norm2[NR];   // pre-scaled by LOG2E
__device__ int   g_fA[64];      // zero-init; set once data is converted
__device__ int   g_fB[64];

// ============================ PTX helpers ============================
__device__ __forceinline__ uint32_t smem_u32(const void* p) {
    uint32_t a;
    asm("{ .reg .u64 t; cvta.to.shared.u64 t, %1; cvt.u32.u64 %0, t; }" : "=r"(a) : "l"(p));
    return a;
}
__device__ __forceinline__ float ex2f(float x) {
    float y; asm("ex2.approx.ftz.f32 %0, %1;" : "=f"(y) : "f"(x)); return y;
}
__device__ __forceinline__ void ldsm_x4(uint32_t& r0, uint32_t& r1, uint32_t& r2, uint32_t& r3,
                                        uint32_t addr) {
    asm volatile("ldmatrix.sync.aligned.m8n8.x4.shared.b16 {%0,%1,%2,%3}, [%4];"
                 : "=r"(r0), "=r"(r1), "=r"(r2), "=r"(r3) : "r"(addr));
}
__device__ __forceinline__ void mma16816(float& c0, float& c1, float& c2, float& c3,
                                         uint32_t a0, uint32_t a1, uint32_t a2, uint32_t a3,
                                         uint32_t b0, uint32_t b1) {
    asm volatile(
        "mma.sync.aligned.m16n8k16.row.col.f32.f16.f16.f32 "
        "{%0,%1,%2,%3}, {%4,%5,%6,%7}, {%8,%9}, {%0,%1,%2,%3};"
        : "+f"(c0), "+f"(c1), "+f"(c2), "+f"(c3)
        : "r"(a0), "r"(a1), "r"(a2), "r"(a3), "r"(b0), "r"(b1));
}
#define MBAR_INIT(mbar, cnt) \
    asm volatile("mbarrier.init.shared.b64 [%0], %1;" :: "r"((uint32_t)(mbar)), "r"((uint32_t)(cnt)) : "memory")
#define MBAR_EXPECT_TX(mbar, bytes) \
    asm volatile("mbarrier.arrive.expect_tx.shared.b64 _, [%0], %1;" \
                 :: "r"((uint32_t)(mbar)), "r"((uint32_t)(bytes)) : "memory")
#define BULK_G2S(dst, src, bytes, mbar) \
    asm volatile("cp.async.bulk.shared::cta.global.mbarrier::complete_tx::bytes [%0], [%1], %2, [%3];" \
                 :: "r"((uint32_t)(dst)), "l"(src), "r"((uint32_t)(bytes)), "r"((uint32_t)(mbar)) : "memory")
__device__ __forceinline__ void mbar_wait(uint32_t mbar, uint32_t parity) {
    asm volatile(
        "{\n\t.reg .pred P;\n\t"
        "W%=:\n\t"
        "mbarrier.try_wait.parity.acquire.cta.shared::cta.b64 P, [%0], %1, 0x989680;\n\t"
        "@P bra.uni D%=;\n\t"
        "bra.uni W%=;\n\t"
        "D%=:\n\t}"
        :: "r"(mbar), "r"(parity) : "memory");
}
__device__ __forceinline__ void wait_flag(const int* p) {
    int v;
    do {
        asm volatile("ld.global.acquire.gpu.b32 %0, [%1];" : "=r"(v) : "l"(p));
    } while (v == 0);
}

// ============================ in-kernel conversion ============================
// Converts one 128-row block: fp32 -> fp16, swizzled image, pre-scaled norms.
__device__ __forceinline__ void convert_block(const float* __restrict__ src,
                                              uint8_t* __restrict__ dstImg,
                                              float* __restrict__ dstNorm,
                                              int blk, bool permuteB, int tid) {
    #pragma unroll
    for (int k = 0; k < 8; k++) {
        int idx = tid + k * 256;          // 2048 tasks: (row, chunk)
        int row = idx >> 4;               // 0..127
        int q   = idx & 15;               // float4 chunk: k = 4q..4q+3
        int r   = blk * 128 + row;
        float4 v = reinterpret_cast<const float4*>(src)[(size_t)r * 16 + q];

        float x[4] = {v.x, v.y, v.z, v.w};
        uint32_t hu[4];
        float ss = 0.f;
        #pragma unroll
        for (int e = 0; e < 4; e++) {
            hu[e] = (uint32_t)__half_as_ushort(__float2half_rn(x[e]));
            ss = fmaf(x[e], x[e], ss);
        }
        uint2 hi = make_uint2(hu[0] | (hu[1] << 16), hu[2] | (hu[3] << 16));

        int lr = row;
        if (permuteB) {                   // B-column permutation (see R10)
            int a = lr & 31;
            int l = (((a >> 1) & 3) << 3) | (((a >> 3) & 3) << 1) | (a & 1);
            lr = (lr & ~31) | l;
        }
        int swc = (q >> 1) ^ (lr & 7);    // XOR swizzle for ldmatrix
        size_t off = (size_t)blk * 16384 + (size_t)lr * 128 + swc * 16 + (q & 1) * 8;
        *reinterpret_cast<uint2*>(dstImg + off) = hi;

        #pragma unroll
        for (int o = 8; o; o >>= 1) ss += __shfl_xor_sync(0xffffffffu, ss, o, 16);
        if (q == 0) dstNorm[r] = ss * LOG2E;   // pre-scaled, ACTUAL row order
    }
}

// ============================ main kernel ============================
// smem: A 2x16KB | B 16KB | n1 1KB | n2 512B | mbarB, mbarA
#define SM_A     0
#define SM_B     32768
#define SM_N1    49152
#define SM_N2    50176
#define SM_MBB   50688
#define SM_MBA   50696
#define SM_TOT   50816

__global__ __launch_bounds__(256, 3) void gk_mma(const float* __restrict__ H1,
                                                 const float* __restrict__ H2,
                                                 float* __restrict__ out) {
    extern __shared__ uint8_t smem[];
    const uint32_t sb = smem_u32(smem);
    const int tid  = threadIdx.x;
    const int wid  = tid >> 5;
    const int lane = tid & 31;
    const int bx = blockIdx.x;            // j tile (64)
    const int by = blockIdx.y;            // i super-tile (32, 256 rows each)
    const int lin = by * 64 + bx;         // HW dispatch order (x fastest)
    const int iT = by * 256;
    const int jT = bx * 128;

    if (tid == 0) { MBAR_INIT(sb + SM_MBB, 1); MBAR_INIT(sb + SM_MBA, 1); }

    // ---- wave-1 conversion: CTAs lin<128 each convert one 128-row block ----
    if (lin < 128) {
        if (lin < 64) convert_block(H1, g_H1s, g_norm1, lin, false, tid);
        else          convert_block(H2, g_H2s, g_norm2, lin - 64, true, tid);
        __threadfence();                               // writes -> gpu scope
        asm volatile("fence.proxy.async;" ::: "memory"); // order vs TMA reads
        __syncthreads();
        if (tid == 0)
            atomicExch(lin < 64 ? &g_fA[lin] : &g_fB[lin - 64], 1);
    }
    __syncthreads();                       // also covers mbar init

    // ---- wait for our 3 blocks, then TMA (B first so bF LDSM can start) ----
    if (tid == 0) {
        wait_flag(&g_fB[bx]);
        wait_flag(&g_fA[2 * by]);
        wait_flag(&g_fA[2 * by + 1]);
        MBAR_EXPECT_TX(sb + SM_MBB, 16384u);
        BULK_G2S(sb + SM_B, g_H2s + (size_t)bx * 16384, 16384u, sb + SM_MBB);
        MBAR_EXPECT_TX(sb + SM_MBA, 32768u);
        BULK_G2S(sb + SM_A, g_H1s + (size_t)by * 32768, 32768u, sb + SM_MBA);
    }
    __syncthreads();                       // flags acquired -> whole CTA

    // ---- stage norms (already pre-scaled by LOG2E) ----
    ((float*)(smem + SM_N1))[tid] = g_norm1[iT + tid];           // 256 rows
    if (tid < 128)
        ((float*)(smem + SM_N2))[tid] = g_norm2[jT + tid];
    __syncthreads();

    // warp tile: 64 rows x 32 cols per i-block.  wr in {0,1}, wc in {0..3}
    const int wr = wid & 1;
    const int wc = wid >> 1;
    const uint32_t aKbit = (uint32_t)(lane >> 4);
    const uint32_t bKbit = (uint32_t)((lane >> 3) & 1);

    // ---- B arrives: preload ALL B fragments (32 regs), reused by 2 i-blocks ----
    mbar_wait(sb + SM_MBB, 0);
    uint32_t bF[4][2][4];
    #pragma unroll
    for (int ng = 0; ng < 2; ng++) {
        int nb = wc * 32 + ng * 16 + (lane & 7) + ((lane >> 4) & 1) * 8;
        uint32_t bRow = sb + SM_B + nb * 128;
        uint32_t bXr  = (uint32_t)(nb & 7);
        #pragma unroll
        for (int kc = 0; kc < 4; kc++) {
            uint32_t ch = (2u * kc + bKbit) ^ bXr;
            ldsm_x4(bF[kc][ng][0], bF[kc][ng][1], bF[kc][ng][2], bF[kc][ng][3],
                    bRow + (ch << 4));
        }
    }

    // epilogue lane mapping (B-permuted layout: lane's 8 cols = colb..colb+7)
    const float* n1c = (const float*)(smem + SM_N1);
    const float* n2c = (const float*)(smem + SM_N2);
    const int t  = lane & 3;
    const int g  = lane >> 2;
    const bool hi_g = (g >= 4);
    const int  gl   = g & 3;
    const int colb = wc * 32 + t * 8;

    mbar_wait(sb + SM_MBA, 0);             // A tiles ready

    // ---- two i-blocks share the hoisted B fragments ----
    #pragma unroll
    for (int ih = 0; ih < 2; ih++) {
        const uint32_t aBlk = sb + SM_A + ih * 16384;

        #pragma unroll
        for (int mi = 0; mi < 4; mi++) {
            const int ra = wr * 64 + mi * 16 + (lane & 15);
            const uint32_t aBase = aBlk + ra * 128;
            const uint32_t aXr   = (uint32_t)(ra & 7);

            float acc[4][4];
            #pragma unroll
            for (int ni = 0; ni < 4; ni++)
                #pragma unroll
                for (int f = 0; f < 4; f++) acc[ni][f] = 0.f;

            #pragma unroll
            for (int kc = 0; kc < 4; kc++) {
                uint32_t aF[4];
                uint32_t ch = (2u * kc + aKbit) ^ aXr;
                ldsm_x4(aF[0], aF[1], aF[2], aF[3], aBase + (ch << 4));
                #pragma unroll
                for (int ni = 0; ni < 4; ni++)
                    mma16816(acc[ni][0], acc[ni][1], acc[ni][2], acc[ni][3],
                             aF[0], aF[1], aF[2], aF[3],
                             bF[kc][ni >> 1][(ni & 1) * 2], bF[kc][ni >> 1][(ni & 1) * 2 + 1]);
            }

            // epilogue for this (ih, mi)
            const int lrow = ih * 128 + wr * 64 + mi * 16 + g;
            const float rnA = n1c[lrow];
            const float rnB = n1c[lrow + 8];

            #pragma unroll
            for (int half = 0; half < 2; half++) {
                const float rn = half ? rnB : rnA;
                float4 w0, w1;
                w0.x = ex2f(fmaf(acc[0][half * 2 + 0], 2.f * LOG2E, -rn) - n2c[colb + 0]);
                w0.y = ex2f(fmaf(acc[0][half * 2 + 1], 2.f * LOG2E, -rn) - n2c[colb + 1]);
                w0.z = ex2f(fmaf(acc[1][half * 2 + 0], 2.f * LOG2E, -rn) - n2c[colb + 2]);
                w0.w = ex2f(fmaf(acc[1][half * 2 + 1], 2.f * LOG2E, -rn) - n2c[colb + 3]);
                w1.x = ex2f(fmaf(acc[2][half * 2 + 0], 2.f * LOG2E, -rn) - n2c[colb + 4]);
                w1.y = ex2f(fmaf(acc[2][half * 2 + 1], 2.f * LOG2E, -rn) - n2c[colb + 5]);
                w1.z = ex2f(fmaf(acc[3][half * 2 + 0], 2.f * LOG2E, -rn) - n2c[colb + 6]);
                w1.w = ex2f(fmaf(acc[3][half * 2 + 1], 2.f * LOG2E, -rn) - n2c[colb + 7]);

                float4 w1x;   // xor(16) row-merge -> 4-wavefront STGs
                w1x.x = __shfl_xor_sync(0xffffffffu, w1.x, 16);
                w1x.y = __shfl_xor_sync(0xffffffffu, w1.y, 16);
                w1x.z = __shfl_xor_sync(0xffffffffu, w1.z, 16);
                w1x.w = __shfl_xor_sync(0xffffffffu, w1.w, 16);

                const int Rbase = iT + ih * 128 + wr * 64 + mi * 16 + half * 8;
                {   // rows Rbase..Rbase+3
                    float4 v = hi_g ? w1x : w0;
                    int col = colb + (hi_g ? 4 : 0);
                    __stcs(reinterpret_cast<float4*>(out + (size_t)(Rbase + gl) * NR + jT + col), v);
                }
                {   // rows Rbase+4..Rbase+7
                    float4 v = hi_g ? w0 : w1x;
                    int col = colb + (hi_g ? 0 : 4);
                    __stcs(reinterpret_cast<float4*>(out + (size_t)(Rbase + gl + 4) * NR + jT + col), v);
                }
            }
        }
    }
}

// ============================ launch ============================
extern "C" void kernel_launch(void* const* d_in, const int* in_sizes, int n_in,
                              void* d_out, int out_size)
{
    const float* H1 = (const float*)d_in[0];
    const float* H2 = (const float*)d_in[1];
    float* out = (float*)d_out;

    int n1 = in_sizes[0] / KDIM;   // 8192
    int n2 = in_sizes[1] / KDIM;   // 8192

    static bool attr_set = false;
    if (!attr_set) {
        cudaFuncSetAttribute(gk_mma, cudaFuncAttributeMaxDynamicSharedMemorySize, SM_TOT);
        attr_set = true;
    }
    dim3 grid(n2 / 128, n1 / 256);   // (64, 32)
    gk_mma<<<grid, 256, SM_TOT>>>(H1, H2, out);
}